// round 1
// baseline (speedup 1.0000x reference)
#include <cuda_runtime.h>
#include <cstdint>

// Problem constants
#define B  8
#define N  4096
#define F  128
#define GS 1024

// Scratch for per-batch top-k indices (in top-k order: descending value)
__device__ int g_idx[B * GS];

// ---------------------------------------------------------------------------
// Kernel 1: exact top-k per batch via full bitonic sort of 64-bit keys.
// key = (~monotone(value) << 32) | index ; ascending sort ==> descending value,
// ties broken by ascending index (matches jax.lax.top_k).
// ---------------------------------------------------------------------------
__global__ __launch_bounds__(1024) void topk_kernel(const float* __restrict__ x)
{
    __shared__ unsigned long long sk[N];
    const int b   = blockIdx.x;
    const int tid = threadIdx.x;

    // Load last-feature values, build sort keys
    #pragma unroll
    for (int t = tid; t < N; t += 1024) {
        float v = x[((size_t)b * N + t) * F + (F - 1)];
        unsigned int u = __float_as_uint(v);
        // monotone map: bigger float -> bigger uint
        u = (u & 0x80000000u) ? ~u : (u | 0x80000000u);
        sk[t] = ((unsigned long long)(~u) << 32) | (unsigned int)t;
    }
    __syncthreads();

    // Bitonic sort, ascending
    for (int k = 2; k <= N; k <<= 1) {
        for (int j = k >> 1; j > 0; j >>= 1) {
            #pragma unroll
            for (int t = tid; t < N; t += 1024) {
                int ixj = t ^ j;
                if (ixj > t) {
                    unsigned long long a = sk[t];
                    unsigned long long c = sk[ixj];
                    bool up = ((t & k) == 0);
                    if ((a > c) == up) { sk[t] = c; sk[ixj] = a; }
                }
            }
            __syncthreads();
        }
    }

    // First GS keys = top-k in jax order
    if (tid < GS) {
        g_idx[b * GS + tid] = (int)(sk[tid] & 0xFFFFFFFFu);
    }
}

// ---------------------------------------------------------------------------
// Kernel 2: one CTA per output row (b, i).
//   - coalesced float4 load of A[b, idx[i], :] (16KB) into smem
//   - smem gather of 1024 selected columns -> At2 row (coalesced stores)
//   - warp 0 copies x[b, idx[i], :] (512B) -> xg row
// ---------------------------------------------------------------------------
__global__ __launch_bounds__(512) void gather_kernel(const float* __restrict__ A,
                                                     const float* __restrict__ x,
                                                     float* __restrict__ out)
{
    __shared__ float row[N];        // 16 KB
    __shared__ int   sidx[GS];      // 4 KB

    const int bi  = blockIdx.x;
    const int b   = bi >> 10;       // / GS
    const int i   = bi & (GS - 1);
    const int tid = threadIdx.x;

    const int ri = g_idx[b * GS + i];

    // Coalesced load of the full A row (1024 float4)
    const float4* arow = (const float4*)(A + ((size_t)b * N + ri) * N);
    float4* rowv = (float4*)row;
    #pragma unroll
    for (int t = tid; t < N / 4; t += 512) rowv[t] = arow[t];

    // Cache column indices
    #pragma unroll
    for (int t = tid; t < GS; t += 512) sidx[t] = g_idx[b * GS + t];

    // xg row copy: 32 float4 by warp 0
    if (tid < F / 4) {
        const float4* xrow = (const float4*)(x + ((size_t)b * N + ri) * F);
        float4* xgrow = (float4*)(out + (size_t)B * GS * GS
                                      + ((size_t)b * GS + i) * F);
        xgrow[tid] = xrow[tid];
    }

    __syncthreads();

    // Gather selected columns -> At2 row (coalesced global stores)
    float* orow = out + ((size_t)b * GS + i) * GS;
    #pragma unroll
    for (int t = tid; t < GS; t += 512) orow[t] = row[sidx[t]];
}

// ---------------------------------------------------------------------------
extern "C" void kernel_launch(void* const* d_in, const int* in_sizes, int n_in,
                              void* d_out, int out_size)
{
    const float* A = (const float*)d_in[0];  // (8,4096,4096) f32
    const float* x = (const float*)d_in[1];  // (8,4096,128)  f32
    float* out = (float*)d_out;              // At2 (8,1024,1024) ++ xg (8,1024,128)

    topk_kernel<<<B, 1024>>>(x);
    gather_kernel<<<B * GS, 512>>>(A, x, out);
}

// round 2
// speedup vs baseline: 1.2431x; 1.2431x over previous
#include <cuda_runtime.h>
#include <cstdint>
#include <cub/block/block_radix_sort.cuh>

// Problem constants
#define B  8
#define N  4096
#define F  128
#define GS 1024

// Scratch for per-batch top-k indices (in top-k order: descending value)
__device__ int g_idx[B * GS];

// ---------------------------------------------------------------------------
// Kernel 1: exact top-k per batch via CUB block radix sort of 44-bit keys.
// key = (~monotone(value) << 12) | index ; ascending sort ==> descending value,
// ties broken by ascending index (matches jax.lax.top_k). Index fits in 12 bits
// (N=4096), so only bits [0,44) participate in the sort.
// ---------------------------------------------------------------------------
__global__ __launch_bounds__(1024) void topk_kernel(const float* __restrict__ x)
{
    typedef cub::BlockRadixSort<unsigned long long, 1024, 4> BlockSort;
    __shared__ typename BlockSort::TempStorage temp;

    const int b   = blockIdx.x;
    const int tid = threadIdx.x;

    unsigned long long keys[4];
    #pragma unroll
    for (int l = 0; l < 4; ++l) {
        int item = tid * 4 + l;
        float v = x[((size_t)b * N + item) * F + (F - 1)];
        unsigned int u = __float_as_uint(v);
        // monotone map: bigger float -> bigger uint
        u = (u & 0x80000000u) ? ~u : (u | 0x80000000u);
        keys[l] = ((unsigned long long)(~u) << 12) | (unsigned int)item;
    }

    BlockSort(temp).Sort(keys, 0, 44);

    // Blocked arrangement: thread t holds ranks 4t..4t+3. First GS = top-k.
    #pragma unroll
    for (int l = 0; l < 4; ++l) {
        int r = tid * 4 + l;
        if (r < GS) g_idx[b * GS + r] = (int)(keys[l] & 0xFFFu);
    }
}

// ---------------------------------------------------------------------------
// Kernel 2: one CTA per output row (b, i).
//   - coalesced float4 load of A[b, idx[i], :] (16KB) into smem
//   - smem gather of 1024 selected columns -> At2 row (coalesced stores)
//   - warp 0 copies x[b, idx[i], :] (512B) -> xg row
// ---------------------------------------------------------------------------
__global__ __launch_bounds__(512) void gather_kernel(const float* __restrict__ A,
                                                     const float* __restrict__ x,
                                                     float* __restrict__ out)
{
    __shared__ float row[N];        // 16 KB
    __shared__ int   sidx[GS];      // 4 KB

    const int bi  = blockIdx.x;
    const int b   = bi >> 10;       // / GS
    const int i   = bi & (GS - 1);
    const int tid = threadIdx.x;

    const int ri = g_idx[b * GS + i];

    // Coalesced load of the full A row (1024 float4)
    const float4* arow = (const float4*)(A + ((size_t)b * N + ri) * N);
    float4* rowv = (float4*)row;
    #pragma unroll
    for (int t = tid; t < N / 4; t += 512) rowv[t] = arow[t];

    // Cache column indices
    #pragma unroll
    for (int t = tid; t < GS; t += 512) sidx[t] = g_idx[b * GS + t];

    // xg row copy: 32 float4 by warp 0
    if (tid < F / 4) {
        const float4* xrow = (const float4*)(x + ((size_t)b * N + ri) * F);
        float4* xgrow = (float4*)(out + (size_t)B * GS * GS
                                      + ((size_t)b * GS + i) * F);
        xgrow[tid] = xrow[tid];
    }

    __syncthreads();

    // Gather selected columns -> At2 row (coalesced global stores)
    float* orow = out + ((size_t)b * GS + i) * GS;
    #pragma unroll
    for (int t = tid; t < GS; t += 512) orow[t] = row[sidx[t]];
}

// ---------------------------------------------------------------------------
extern "C" void kernel_launch(void* const* d_in, const int* in_sizes, int n_in,
                              void* d_out, int out_size)
{
    const float* A = (const float*)d_in[0];  // (8,4096,4096) f32
    const float* x = (const float*)d_in[1];  // (8,4096,128)  f32
    float* out = (float*)d_out;              // At2 (8,1024,1024) ++ xg (8,1024,128)

    topk_kernel<<<B, 1024>>>(x);
    gather_kernel<<<B * GS, 512>>>(A, x, out);
}

// round 3
// speedup vs baseline: 1.4400x; 1.1584x over previous
#include <cuda_runtime.h>
#include <cstdint>

// Problem constants
#define B  8
#define N  4096
#define F  128
#define GS 1024

// Scratch
__device__ unsigned long long g_sel[B * GS]; // selected keys, unordered
__device__ int g_idx[B * GS];                // final top-k indices, jax order

// ---------------------------------------------------------------------------
// Kernel 1: per-batch exact threshold via MSB radix select + compaction.
// key = (monotone(v) << 12) | (4095 - i); top-1024 largest keys == jax top_k
// (value desc, tie -> smaller index). Keys are unique (index bits).
// ---------------------------------------------------------------------------
__global__ __launch_bounds__(512) void select_kernel(const float* __restrict__ x)
{
    __shared__ unsigned long long sk[N];   // 32 KB
    __shared__ unsigned int hist[256];
    __shared__ unsigned int s_bin, s_above, s_cnt;

    const int b   = blockIdx.x;
    const int tid = threadIdx.x;

    // Build keys
    #pragma unroll
    for (int l = 0; l < 8; ++l) {
        int i = tid + l * 512;
        float v = x[((size_t)b * N + i) * F + (F - 1)];
        unsigned int u = __float_as_uint(v);
        u = (u & 0x80000000u) ? ~u : (u | 0x80000000u);   // monotone: bigger float -> bigger uint
        sk[i] = ((unsigned long long)u << 12) | (unsigned int)(N - 1 - i);
    }
    if (tid == 0) s_cnt = 0;
    __syncthreads();

    // MSB radix select (descending): find exact 1024th-largest 44-bit key.
    unsigned long long prefix = 0, pmask = 0;
    unsigned int need = GS;

    #pragma unroll
    for (int pass = 0; pass < 6; ++pass) {
        const int          shift = (pass < 5) ? (36 - 8 * pass) : 0;
        const unsigned int dmask = (pass < 5) ? 0xFFu : 0xFu;

        if (tid < 256) hist[tid] = 0;
        __syncthreads();

        #pragma unroll
        for (int l = 0; l < 8; ++l) {
            unsigned long long k = sk[tid + l * 512];
            if ((k & pmask) == prefix)
                atomicAdd(&hist[(unsigned int)(k >> shift) & dmask], 1u);
        }
        __syncthreads();

        if (tid < 32) {
            // lane g covers bins [8g, 8g+8)
            unsigned int sum = 0;
            #pragma unroll
            for (int j = 0; j < 8; ++j) sum += hist[tid * 8 + j];
            // inclusive suffix-sum across lanes
            unsigned int acc = sum;
            #pragma unroll
            for (int off = 1; off < 32; off <<= 1) {
                unsigned int t = __shfl_down_sync(0xFFFFFFFFu, acc, off);
                if (tid + off < 32) acc += t;
            }
            unsigned int running = acc - sum;   // count strictly above my group
            // scan my 8 bins top-down
            #pragma unroll
            for (int j = 7; j >= 0; --j) {
                unsigned int c = hist[tid * 8 + j];
                if (running < need && need <= running + c) {
                    s_bin = (unsigned int)(tid * 8 + j);
                    s_above = running;
                }
                running += c;
            }
        }
        __syncthreads();

        prefix |= ((unsigned long long)s_bin) << shift;
        pmask  |= ((unsigned long long)dmask) << shift;
        need   -= s_above;
        __syncthreads();
    }
    // prefix == exact 1024th-largest key T. Selected set: key >= T (exactly GS keys).

    #pragma unroll
    for (int l = 0; l < 8; ++l) {
        unsigned long long k = sk[tid + l * 512];
        if (k >= prefix) {
            unsigned int pos = atomicAdd(&s_cnt, 1u);
            g_sel[b * GS + pos] = k;
        }
    }
}

// ---------------------------------------------------------------------------
// Kernel 2: rank-by-count over the 1024 selected keys -> final ordered indices.
// rank = #{keys greater than mine} (unique keys => unique ranks).
// ---------------------------------------------------------------------------
__global__ __launch_bounds__(128) void rank_kernel()
{
    __shared__ unsigned long long sk[GS];  // 8 KB

    const int b   = blockIdx.x >> 3;
    const int c   = blockIdx.x & 7;
    const int tid = threadIdx.x;

    #pragma unroll
    for (int l = 0; l < GS / 128; ++l)
        sk[tid + l * 128] = g_sel[b * GS + tid + l * 128];
    __syncthreads();

    const unsigned long long mine = sk[c * 128 + tid];
    int rank = 0;
    #pragma unroll 8
    for (int j = 0; j < GS; ++j)
        rank += (sk[j] > mine);

    g_idx[b * GS + rank] = (N - 1) - (int)(mine & 0xFFFu);
}

// ---------------------------------------------------------------------------
// Kernel 3: one CTA per output row (b, i).
//   - coalesced float4 load of A[b, idx[i], :] (16KB) into smem
//   - smem gather of 1024 selected columns -> At2 row (coalesced stores)
//   - warp 0 copies x[b, idx[i], :] (512B) -> xg row
// ---------------------------------------------------------------------------
__global__ __launch_bounds__(512) void gather_kernel(const float* __restrict__ A,
                                                     const float* __restrict__ x,
                                                     float* __restrict__ out)
{
    __shared__ float row[N];        // 16 KB
    __shared__ int   sidx[GS];      // 4 KB

    const int bi  = blockIdx.x;
    const int b   = bi >> 10;
    const int i   = bi & (GS - 1);
    const int tid = threadIdx.x;

    const int ri = g_idx[b * GS + i];

    const float4* arow = (const float4*)(A + ((size_t)b * N + ri) * N);
    float4* rowv = (float4*)row;
    #pragma unroll
    for (int t = tid; t < N / 4; t += 512) rowv[t] = arow[t];

    #pragma unroll
    for (int t = tid; t < GS; t += 512) sidx[t] = g_idx[b * GS + t];

    if (tid < F / 4) {
        const float4* xrow = (const float4*)(x + ((size_t)b * N + ri) * F);
        float4* xgrow = (float4*)(out + (size_t)B * GS * GS
                                      + ((size_t)b * GS + i) * F);
        xgrow[tid] = xrow[tid];
    }

    __syncthreads();

    float* orow = out + ((size_t)b * GS + i) * GS;
    #pragma unroll
    for (int t = tid; t < GS; t += 512) orow[t] = row[sidx[t]];
}

// ---------------------------------------------------------------------------
extern "C" void kernel_launch(void* const* d_in, const int* in_sizes, int n_in,
                              void* d_out, int out_size)
{
    const float* A = (const float*)d_in[0];  // (8,4096,4096) f32
    const float* x = (const float*)d_in[1];  // (8,4096,128)  f32
    float* out = (float*)d_out;              // At2 (8,1024,1024) ++ xg (8,1024,128)

    select_kernel<<<B, 512>>>(x);
    rank_kernel<<<B * 8, 128>>>();
    gather_kernel<<<B * GS, 512>>>(A, x, out);
}